// round 1
// baseline (speedup 1.0000x reference)
#include <cuda_runtime.h>
#include <cuda_bf16.h>

#define DIM    192
#define HEADS  4
#define D      48
#define D2     24      // D/2 packed f32x2 lanes
#define HW     4096
#define BQ     64      // queries per CTA (= threads per CTA)
#define BK     64      // keys per smem tile
#define KPAD   52      // floats per key row in smem (>=48, 8B-aligned stride)

// ---------------- scratch (static device globals; no allocation) ----------------
__device__ float g_qkv1[3 * DIM * HW];   // after 1x1 qkv conv
__device__ float g_qkv2[3 * DIM * HW];   // after 3x3 depthwise
__device__ float g_invq[HEADS * HW];
__device__ float g_invk[HEADS * HW];
__device__ float g_att [DIM * HW];       // attention output, channel-major

// ---------------- packed f32x2 helpers ----------------
__device__ __forceinline__ unsigned long long ffma2(unsigned long long a,
                                                    unsigned long long b,
                                                    unsigned long long c) {
    unsigned long long d;
    asm("fma.rn.f32x2 %0, %1, %2, %3;" : "=l"(d) : "l"(a), "l"(b), "l"(c));
    return d;
}
__device__ __forceinline__ unsigned long long mul2(unsigned long long a,
                                                   unsigned long long b) {
    unsigned long long d;
    asm("mul.rn.f32x2 %0, %1, %2;" : "=l"(d) : "l"(a), "l"(b));
    return d;
}
__device__ __forceinline__ unsigned long long pack2(float lo, float hi) {
    unsigned long long d;
    asm("mov.b64 %0, {%1, %2};" : "=l"(d) : "f"(lo), "f"(hi));
    return d;
}
__device__ __forceinline__ void unpack2(unsigned long long v, float& lo, float& hi) {
    asm("mov.b64 {%0, %1}, %2;" : "=f"(lo), "=f"(hi) : "l"(v));
}

// ---------------- GEMM: C[M,N] = W[M,K] * X[K,N] + bias[M] ----------------
__global__ __launch_bounds__(256) void gemm_bias_kernel(
    const float* __restrict__ W, const float* __restrict__ X,
    const float* __restrict__ bias, float* __restrict__ C,
    int M, int N, int K)
{
    __shared__ float Ws[16][65];   // padded: avoid 16-way write conflicts
    __shared__ float Xs[16][64];
    int m0 = blockIdx.y * 64, n0 = blockIdx.x * 64;
    int tx = threadIdx.x & 15, ty = threadIdx.x >> 4;
    float acc[4][4];
    #pragma unroll
    for (int i = 0; i < 4; i++)
        #pragma unroll
        for (int j = 0; j < 4; j++) acc[i][j] = 0.f;

    for (int k0 = 0; k0 < K; k0 += 16) {
        #pragma unroll
        for (int r = 0; r < 4; r++) {
            int i = threadIdx.x + r * 256;
            int k = i & 15, mm = i >> 4;
            Ws[k][mm] = W[(m0 + mm) * K + k0 + k];
        }
        #pragma unroll
        for (int r = 0; r < 4; r++) {
            int i = threadIdx.x + r * 256;
            int n = i & 63, k = i >> 6;
            Xs[k][n] = X[(size_t)(k0 + k) * N + n0 + n];
        }
        __syncthreads();
        #pragma unroll
        for (int k = 0; k < 16; k++) {
            float wr[4], xr[4];
            #pragma unroll
            for (int i = 0; i < 4; i++) wr[i] = Ws[k][ty * 4 + i];
            #pragma unroll
            for (int j = 0; j < 4; j++) xr[j] = Xs[k][tx * 4 + j];
            #pragma unroll
            for (int i = 0; i < 4; i++)
                #pragma unroll
                for (int j = 0; j < 4; j++) acc[i][j] += wr[i] * xr[j];
        }
        __syncthreads();
    }
    #pragma unroll
    for (int i = 0; i < 4; i++) {
        float b = bias[m0 + ty * 4 + i];
        #pragma unroll
        for (int j = 0; j < 4; j++)
            C[(size_t)(m0 + ty * 4 + i) * N + n0 + tx * 4 + j] = acc[i][j] + b;
    }
}

// ---------------- 3x3 depthwise conv, padding 1 ----------------
__global__ __launch_bounds__(256) void dwconv_kernel(
    const float* __restrict__ in, const float* __restrict__ w,
    const float* __restrict__ b, float* __restrict__ out)
{
    int c = blockIdx.y;
    int pix = blockIdx.x * 256 + threadIdx.x;   // 0..4095
    int y = pix >> 6, x = pix & 63;
    const float* wp = w + c * 9;
    const float* ip = in + (size_t)c * HW;
    float acc = b[c];
    #pragma unroll
    for (int ky = 0; ky < 3; ky++) {
        int yy = y + ky - 1;
        if (yy < 0 || yy > 63) continue;
        #pragma unroll
        for (int kx = 0; kx < 3; kx++) {
            int xx = x + kx - 1;
            if (xx < 0 || xx > 63) continue;
            acc += wp[ky * 3 + kx] * ip[yy * 64 + xx];
        }
    }
    out[(size_t)c * HW + pix] = acc;
}

// ---------------- per-(head,n) inverse L2 norms for q and k ----------------
__global__ __launch_bounds__(256) void norm_kernel(
    const float* __restrict__ qkv, float* __restrict__ invq, float* __restrict__ invk)
{
    int idx = blockIdx.x * 256 + threadIdx.x;    // 0 .. HEADS*HW-1
    int h = idx / HW, n = idx % HW;
    const float* qb = qkv + (size_t)(h * D) * HW + n;
    const float* kb = qkv + (size_t)(DIM + h * D) * HW + n;
    float sq = 0.f, sk = 0.f;
    #pragma unroll
    for (int d = 0; d < D; d++) {
        float a = qb[(size_t)d * HW]; sq += a * a;
        float c = kb[(size_t)d * HW]; sk += c * c;
    }
    invq[idx] = 1.0f / fmaxf(sqrtf(sq), 1e-12f);
    invk[idx] = 1.0f / fmaxf(sqrtf(sk), 1e-12f);
}

// ---------------- fused flash attention (one query per thread) ----------------
__global__ __launch_bounds__(BQ) void flash_kernel(
    const float* __restrict__ qkv, const float* __restrict__ invq,
    const float* __restrict__ invk, const float* __restrict__ temp,
    float* __restrict__ att)
{
    __shared__ __align__(16) float Ks[BK * KPAD];
    __shared__ __align__(16) float Vs[BK * KPAD];

    int h = blockIdx.y;
    int n = blockIdx.x * BQ + threadIdx.x;
    const float* qbase = qkv + (size_t)(h * D) * HW;
    const float* kbase = qkv + (size_t)(DIM + h * D) * HW;
    const float* vbase = qkv + (size_t)(2 * DIM + h * D) * HW;
    const float* ik    = invk + h * HW;

    float qscale = invq[h * HW + n] * temp[h];

    unsigned long long q2[D2], o2[D2];
    #pragma unroll
    for (int d2 = 0; d2 < D2; d2++) {
        float a = qbase[(size_t)(2 * d2) * HW + n] * qscale;
        float b = qbase[(size_t)(2 * d2 + 1) * HW + n] * qscale;
        q2[d2] = pack2(a, b);
        o2[d2] = 0ULL;   // (0.f, 0.f)
    }
    float m = -1e30f, l = 0.f;

    for (int m0 = 0; m0 < HW; m0 += BK) {
        __syncthreads();
        // cooperative tile load: BK*D = 3072 elems each; 64 threads x 48
        for (int i = threadIdx.x; i < BK * D; i += BQ) {
            int j = i & (BK - 1);
            int d = i >> 6;
            Ks[j * KPAD + d] = kbase[(size_t)d * HW + m0 + j] * ik[m0 + j];
            Vs[j * KPAD + d] = vbase[(size_t)d * HW + m0 + j];
        }
        __syncthreads();

        for (int j = 0; j < BK; j++) {
            const unsigned long long* kp =
                (const unsigned long long*)(Ks + j * KPAD);
            unsigned long long sA = 0ULL, sB = 0ULL;
            #pragma unroll
            for (int t = 0; t < D2; t += 2) {
                sA = ffma2(q2[t],     kp[t],     sA);
                sB = ffma2(q2[t + 1], kp[t + 1], sB);
            }
            float sx, sy, sz, sw;
            unpack2(sA, sx, sy);
            unpack2(sB, sz, sw);
            float s = (sx + sy) + (sz + sw);

            float mn = fmaxf(m, s);
            if (mn > m) {
                float corr = __expf(m - mn);
                l *= corr;
                unsigned long long c2 = pack2(corr, corr);
                #pragma unroll
                for (int d2 = 0; d2 < D2; d2++) o2[d2] = mul2(o2[d2], c2);
                m = mn;
            }
            float p = __expf(s - m);
            l += p;
            unsigned long long p2 = pack2(p, p);
            const unsigned long long* vp =
                (const unsigned long long*)(Vs + j * KPAD);
            #pragma unroll
            for (int d2 = 0; d2 < D2; d2++)
                o2[d2] = ffma2(p2, vp[d2], o2[d2]);
        }
    }

    float linv = 1.0f / l;
    #pragma unroll
    for (int d2 = 0; d2 < D2; d2++) {
        float a, b;
        unpack2(o2[d2], a, b);
        att[(size_t)(h * D + 2 * d2) * HW + n]     = a * linv;
        att[(size_t)(h * D + 2 * d2 + 1) * HW + n] = b * linv;
    }
}

// ---------------- launch ----------------
extern "C" void kernel_launch(void* const* d_in, const int* in_sizes, int n_in,
                              void* d_out, int out_size)
{
    const float* x      = (const float*)d_in[0];
    const float* w_qkv  = (const float*)d_in[1];
    const float* b_qkv  = (const float*)d_in[2];
    const float* w_dw   = (const float*)d_in[3];
    const float* b_dw   = (const float*)d_in[4];
    const float* w_proj = (const float*)d_in[5];
    const float* b_proj = (const float*)d_in[6];
    const float* temp   = (const float*)d_in[7];
    float* out = (float*)d_out;

    float *qkv1, *qkv2, *invq, *invk, *att;
    cudaGetSymbolAddress((void**)&qkv1, g_qkv1);
    cudaGetSymbolAddress((void**)&qkv2, g_qkv2);
    cudaGetSymbolAddress((void**)&invq, g_invq);
    cudaGetSymbolAddress((void**)&invk, g_invk);
    cudaGetSymbolAddress((void**)&att,  g_att);

    // 1) qkv 1x1 conv: [576,4096] = W[576,192] * X[192,4096] + b
    {
        dim3 grid(HW / 64, (3 * DIM) / 64);
        gemm_bias_kernel<<<grid, 256>>>(w_qkv, x, b_qkv, qkv1, 3 * DIM, HW, DIM);
    }
    // 2) 3x3 depthwise
    {
        dim3 grid(HW / 256, 3 * DIM);
        dwconv_kernel<<<grid, 256>>>(qkv1, w_dw, b_dw, qkv2);
    }
    // 3) inverse norms
    norm_kernel<<<(HEADS * HW) / 256, 256>>>(qkv2, invq, invk);
    // 4) fused attention
    {
        dim3 grid(HW / BQ, HEADS);
        flash_kernel<<<grid, BQ>>>(qkv2, invq, invk, temp, att);
    }
    // 5) output projection
    {
        dim3 grid(HW / 64, DIM / 64);
        gemm_bias_kernel<<<grid, 256>>>(w_proj, att, b_proj, out, DIM, HW, DIM);
    }
}

// round 2
// speedup vs baseline: 1.5205x; 1.5205x over previous
#include <cuda_runtime.h>
#include <cuda_bf16.h>

#define DIM    192
#define HEADS  4
#define D      48
#define D2     24      // D/2 packed f32x2 lanes
#define HW     4096
#define BK     64      // keys per smem tile
#define KPAD   52      // floats per key row in smem (>=48, 8B-aligned stride)
#define SPLITS 8
#define SKEYS  (HW / SPLITS)   // 512 keys per split
#define BQF    128             // queries (=threads) per flash CTA

// ---------------- scratch (static device globals; no allocation) ----------------
__device__ float g_qkv1[3 * DIM * HW];   // after 1x1 qkv conv
__device__ float g_qkv2[3 * DIM * HW];   // after 3x3 depthwise
__device__ float g_invq[HEADS * HW];
__device__ float g_invk[HEADS * HW];
__device__ float g_att [DIM * HW];       // attention output, channel-major
__device__ float g_po  [SPLITS * DIM * HW];    // partial unnormalized outputs
__device__ float g_pm  [SPLITS * HEADS * HW];  // partial max
__device__ float g_pl  [SPLITS * HEADS * HW];  // partial sum

// ---------------- packed f32x2 helpers ----------------
__device__ __forceinline__ unsigned long long ffma2(unsigned long long a,
                                                    unsigned long long b,
                                                    unsigned long long c) {
    unsigned long long d;
    asm("fma.rn.f32x2 %0, %1, %2, %3;" : "=l"(d) : "l"(a), "l"(b), "l"(c));
    return d;
}
__device__ __forceinline__ unsigned long long mul2(unsigned long long a,
                                                   unsigned long long b) {
    unsigned long long d;
    asm("mul.rn.f32x2 %0, %1, %2;" : "=l"(d) : "l"(a), "l"(b));
    return d;
}
__device__ __forceinline__ unsigned long long pack2(float lo, float hi) {
    unsigned long long d;
    asm("mov.b64 %0, {%1, %2};" : "=l"(d) : "f"(lo), "f"(hi));
    return d;
}
__device__ __forceinline__ void unpack2(unsigned long long v, float& lo, float& hi) {
    asm("mov.b64 {%0, %1}, %2;" : "=f"(lo), "=f"(hi) : "l"(v));
}

// ---------------- GEMM: C[M,N] = W[M,K] * X[K,N] + bias[M] ----------------
__global__ __launch_bounds__(256) void gemm_bias_kernel(
    const float* __restrict__ W, const float* __restrict__ X,
    const float* __restrict__ bias, float* __restrict__ C,
    int M, int N, int K)
{
    __shared__ float Ws[16][65];
    __shared__ float Xs[16][64];
    int m0 = blockIdx.y * 64, n0 = blockIdx.x * 64;
    int tx = threadIdx.x & 15, ty = threadIdx.x >> 4;
    float acc[4][4];
    #pragma unroll
    for (int i = 0; i < 4; i++)
        #pragma unroll
        for (int j = 0; j < 4; j++) acc[i][j] = 0.f;

    for (int k0 = 0; k0 < K; k0 += 16) {
        #pragma unroll
        for (int r = 0; r < 4; r++) {
            int i = threadIdx.x + r * 256;
            int k = i & 15, mm = i >> 4;
            Ws[k][mm] = W[(m0 + mm) * K + k0 + k];
        }
        #pragma unroll
        for (int r = 0; r < 4; r++) {
            int i = threadIdx.x + r * 256;
            int n = i & 63, k = i >> 6;
            Xs[k][n] = X[(size_t)(k0 + k) * N + n0 + n];
        }
        __syncthreads();
        #pragma unroll
        for (int k = 0; k < 16; k++) {
            float wr[4], xr[4];
            #pragma unroll
            for (int i = 0; i < 4; i++) wr[i] = Ws[k][ty * 4 + i];
            #pragma unroll
            for (int j = 0; j < 4; j++) xr[j] = Xs[k][tx * 4 + j];
            #pragma unroll
            for (int i = 0; i < 4; i++)
                #pragma unroll
                for (int j = 0; j < 4; j++) acc[i][j] += wr[i] * xr[j];
        }
        __syncthreads();
    }
    #pragma unroll
    for (int i = 0; i < 4; i++) {
        float b = bias[m0 + ty * 4 + i];
        #pragma unroll
        for (int j = 0; j < 4; j++)
            C[(size_t)(m0 + ty * 4 + i) * N + n0 + tx * 4 + j] = acc[i][j] + b;
    }
}

// ---------------- 3x3 depthwise conv, padding 1 ----------------
__global__ __launch_bounds__(256) void dwconv_kernel(
    const float* __restrict__ in, const float* __restrict__ w,
    const float* __restrict__ b, float* __restrict__ out)
{
    int c = blockIdx.y;
    int pix = blockIdx.x * 256 + threadIdx.x;
    int y = pix >> 6, x = pix & 63;
    const float* wp = w + c * 9;
    const float* ip = in + (size_t)c * HW;
    float acc = b[c];
    #pragma unroll
    for (int ky = 0; ky < 3; ky++) {
        int yy = y + ky - 1;
        if (yy < 0 || yy > 63) continue;
        #pragma unroll
        for (int kx = 0; kx < 3; kx++) {
            int xx = x + kx - 1;
            if (xx < 0 || xx > 63) continue;
            acc += wp[ky * 3 + kx] * ip[yy * 64 + xx];
        }
    }
    out[(size_t)c * HW + pix] = acc;
}

// ---------------- per-(head,n) inverse L2 norms for q and k ----------------
__global__ __launch_bounds__(256) void norm_kernel(
    const float* __restrict__ qkv, float* __restrict__ invq, float* __restrict__ invk)
{
    int idx = blockIdx.x * 256 + threadIdx.x;
    int h = idx / HW, n = idx % HW;
    const float* qb = qkv + (size_t)(h * D) * HW + n;
    const float* kb = qkv + (size_t)(DIM + h * D) * HW + n;
    float sq = 0.f, sk = 0.f;
    #pragma unroll
    for (int d = 0; d < D; d++) {
        float a = qb[(size_t)d * HW]; sq += a * a;
        float c = kb[(size_t)d * HW]; sk += c * c;
    }
    invq[idx] = 1.0f / fmaxf(sqrtf(sq), 1e-12f);
    invk[idx] = 1.0f / fmaxf(sqrtf(sk), 1e-12f);
}

// ---------------- flash attention, split over keys (one query per thread) ----
__global__ __launch_bounds__(BQF) void flash_part_kernel(
    const float* __restrict__ qkv, const float* __restrict__ invq,
    const float* __restrict__ invk, const float* __restrict__ temp,
    float* __restrict__ po, float* __restrict__ pm, float* __restrict__ pl)
{
    __shared__ __align__(16) float Ks[BK * KPAD];
    __shared__ __align__(16) float Vs[BK * KPAD];

    int h = blockIdx.y;
    int s = blockIdx.z;
    int n = blockIdx.x * BQF + threadIdx.x;
    const float* qbase = qkv + (size_t)(h * D) * HW;
    const float* kbase = qkv + (size_t)(DIM + h * D) * HW;
    const float* vbase = qkv + (size_t)(2 * DIM + h * D) * HW;
    const float* ik    = invk + h * HW;

    float qscale = invq[h * HW + n] * temp[h];

    unsigned long long q2[D2], o2[D2];
    #pragma unroll
    for (int d2 = 0; d2 < D2; d2++) {
        float a = qbase[(size_t)(2 * d2) * HW + n] * qscale;
        float b = qbase[(size_t)(2 * d2 + 1) * HW + n] * qscale;
        q2[d2] = pack2(a, b);
        o2[d2] = 0ULL;
    }
    float m = -1e30f, l = 0.f;

    int kbeg = s * SKEYS, kend = kbeg + SKEYS;
    for (int m0 = kbeg; m0 < kend; m0 += BK) {
        __syncthreads();
        for (int i = threadIdx.x; i < BK * D; i += BQF) {
            int j = i & (BK - 1);
            int d = i >> 6;
            Ks[j * KPAD + d] = kbase[(size_t)d * HW + m0 + j] * ik[m0 + j];
            Vs[j * KPAD + d] = vbase[(size_t)d * HW + m0 + j];
        }
        __syncthreads();

        for (int j = 0; j < BK; j++) {
            const unsigned long long* kp =
                (const unsigned long long*)(Ks + j * KPAD);
            unsigned long long sA = 0ULL, sB = 0ULL;
            #pragma unroll
            for (int t = 0; t < D2; t += 2) {
                sA = ffma2(q2[t],     kp[t],     sA);
                sB = ffma2(q2[t + 1], kp[t + 1], sB);
            }
            float sx, sy, sz, sw;
            unpack2(sA, sx, sy);
            unpack2(sB, sz, sw);
            float sc = (sx + sy) + (sz + sw);

            float mn = fmaxf(m, sc);
            if (mn > m) {
                float corr = __expf(m - mn);
                l *= corr;
                unsigned long long c2 = pack2(corr, corr);
                #pragma unroll
                for (int d2 = 0; d2 < D2; d2++) o2[d2] = mul2(o2[d2], c2);
                m = mn;
            }
            float p = __expf(sc - m);
            l += p;
            unsigned long long p2 = pack2(p, p);
            const unsigned long long* vp =
                (const unsigned long long*)(Vs + j * KPAD);
            #pragma unroll
            for (int d2 = 0; d2 < D2; d2++)
                o2[d2] = ffma2(p2, vp[d2], o2[d2]);
        }
    }

    // write partial results (unnormalized)
    int sh = s * HEADS + h;
    pm[(size_t)sh * HW + n] = m;
    pl[(size_t)sh * HW + n] = l;
    float* pob = po + (size_t)sh * D * HW + n;
    #pragma unroll
    for (int d2 = 0; d2 < D2; d2++) {
        float a, b;
        unpack2(o2[d2], a, b);
        pob[(size_t)(2 * d2) * HW]     = a;
        pob[(size_t)(2 * d2 + 1) * HW] = b;
    }
}

// ---------------- combine split partials ----------------
__global__ __launch_bounds__(256) void combine_kernel(
    const float* __restrict__ po, const float* __restrict__ pm,
    const float* __restrict__ pl, float* __restrict__ att)
{
    int idx = blockIdx.x * 256 + threadIdx.x;   // 0 .. HEADS*HW-1
    int h = idx / HW, n = idx % HW;

    float ms[SPLITS], ls[SPLITS];
    float M = -1e30f;
    #pragma unroll
    for (int s = 0; s < SPLITS; s++) {
        ms[s] = pm[(size_t)(s * HEADS + h) * HW + n];
        ls[s] = pl[(size_t)(s * HEADS + h) * HW + n];
        M = fmaxf(M, ms[s]);
    }
    float L = 0.f;
    float w[SPLITS];
    #pragma unroll
    for (int s = 0; s < SPLITS; s++) {
        w[s] = __expf(ms[s] - M);
        L += ls[s] * w[s];
    }
    float Linv = 1.0f / L;
    #pragma unroll
    for (int s = 0; s < SPLITS; s++) w[s] *= Linv;

    #pragma unroll
    for (int d = 0; d < D; d++) {
        float acc = 0.f;
        #pragma unroll
        for (int s = 0; s < SPLITS; s++)
            acc += po[(size_t)((s * HEADS + h) * D + d) * HW + n] * w[s];
        att[(size_t)(h * D + d) * HW + n] = acc;
    }
}

// ---------------- launch ----------------
extern "C" void kernel_launch(void* const* d_in, const int* in_sizes, int n_in,
                              void* d_out, int out_size)
{
    const float* x      = (const float*)d_in[0];
    const float* w_qkv  = (const float*)d_in[1];
    const float* b_qkv  = (const float*)d_in[2];
    const float* w_dw   = (const float*)d_in[3];
    const float* b_dw   = (const float*)d_in[4];
    const float* w_proj = (const float*)d_in[5];
    const float* b_proj = (const float*)d_in[6];
    const float* temp   = (const float*)d_in[7];
    float* out = (float*)d_out;

    float *qkv1, *qkv2, *invq, *invk, *att, *po, *pm, *pl;
    cudaGetSymbolAddress((void**)&qkv1, g_qkv1);
    cudaGetSymbolAddress((void**)&qkv2, g_qkv2);
    cudaGetSymbolAddress((void**)&invq, g_invq);
    cudaGetSymbolAddress((void**)&invk, g_invk);
    cudaGetSymbolAddress((void**)&att,  g_att);
    cudaGetSymbolAddress((void**)&po,   g_po);
    cudaGetSymbolAddress((void**)&pm,   g_pm);
    cudaGetSymbolAddress((void**)&pl,   g_pl);

    // 1) qkv 1x1 conv: [576,4096] = W[576,192] * X[192,4096] + b
    {
        dim3 grid(HW / 64, (3 * DIM) / 64);
        gemm_bias_kernel<<<grid, 256>>>(w_qkv, x, b_qkv, qkv1, 3 * DIM, HW, DIM);
    }
    // 2) 3x3 depthwise
    {
        dim3 grid(HW / 256, 3 * DIM);
        dwconv_kernel<<<grid, 256>>>(qkv1, w_dw, b_dw, qkv2);
    }
    // 3) inverse norms
    norm_kernel<<<(HEADS * HW) / 256, 256>>>(qkv2, invq, invk);
    // 4) fused attention, split over keys
    {
        dim3 grid(HW / BQF, HEADS, SPLITS);
        flash_part_kernel<<<grid, BQF>>>(qkv2, invq, invk, temp, po, pm, pl);
    }
    // 5) combine partials
    combine_kernel<<<(HEADS * HW) / 256, 256>>>(po, pm, pl, att);
    // 6) output projection
    {
        dim3 grid(HW / 64, DIM / 64);
        gemm_bias_kernel<<<grid, 256>>>(w_proj, att, b_proj, out, DIM, HW, DIM);
    }
}

// round 5
// speedup vs baseline: 4.7602x; 3.1307x over previous
#include <cuda_runtime.h>
#include <cuda_bf16.h>
#include <cstdint>

#define DIM    192
#define HEADS  4
#define D      48
#define HW     4096
#define BKT    64              // keys per tile
#define SPLITS 4
#define SKEYS  (HW / SPLITS)   // 1024 keys per split
#define NTT    (SKEYS / BKT)   // 16 tiles

// dynamic smem layout (floats)
#define QF_OFF 0               // Q frags: 4w x 2rb x 6s x 32lane x 4 = 6144
#define KF_OFF 6144            // K frags: 6s x 8j x 32lane x 2     = 3072
#define VF_OFF 9216            // V frags: 8s2 x 6j2 x 32lane x 2   = 3072
#define SMEM_FLOATS 12288      // 49152 bytes

// ---------------- scratch ----------------
__device__ float g_qkv1[3 * DIM * HW];
__device__ float g_qkv2[3 * DIM * HW];
__device__ float g_invq[HEADS * HW];
__device__ float g_invk[HEADS * HW];
__device__ float g_att [DIM * HW];
__device__ float g_po  [SPLITS * DIM * HW];
__device__ float g_pl  [SPLITS * HEADS * HW];

// ---------------- helpers ----------------
__device__ __forceinline__ uint32_t f2tf(float x) {
    uint32_t y; asm("cvt.rna.tf32.f32 %0, %1;" : "=r"(y) : "f"(x)); return y;
}
__device__ __forceinline__ float ex2f(float x) {
    float y; asm("ex2.approx.f32 %0, %1;" : "=f"(y) : "f"(x)); return y;
}
// D += A(16x8 tf32) * B(8x8 tf32)
__device__ __forceinline__ void mma8(float* d, const float* a, float2 b) {
    asm volatile("mma.sync.aligned.m16n8k8.row.col.f32.tf32.tf32.f32 "
        "{%0,%1,%2,%3}, {%4,%5,%6,%7}, {%8,%9}, {%0,%1,%2,%3};"
        : "+f"(d[0]), "+f"(d[1]), "+f"(d[2]), "+f"(d[3])
        : "r"(__float_as_uint(a[0])), "r"(__float_as_uint(a[1])),
          "r"(__float_as_uint(a[2])), "r"(__float_as_uint(a[3])),
          "r"(__float_as_uint(b.x)),  "r"(__float_as_uint(b.y)));
}
// Build A-fragment (cols t, t+4) from C-fragment (cols 2t, 2t+1) via quad shuffles.
__device__ __forceinline__ void make_pa(const float* s4, float* pa, int lane) {
    int sA = (lane & 28) | ((lane & 3) >> 1);
    int sB = sA + 2;
    float v00 = __shfl_sync(0xffffffffu, s4[0], sA);
    float v01 = __shfl_sync(0xffffffffu, s4[1], sA);
    float v10 = __shfl_sync(0xffffffffu, s4[2], sA);
    float v11 = __shfl_sync(0xffffffffu, s4[3], sA);
    float w00 = __shfl_sync(0xffffffffu, s4[0], sB);
    float w01 = __shfl_sync(0xffffffffu, s4[1], sB);
    float w10 = __shfl_sync(0xffffffffu, s4[2], sB);
    float w11 = __shfl_sync(0xffffffffu, s4[3], sB);
    bool hi = lane & 1;
    pa[0] = hi ? v01 : v00;
    pa[1] = hi ? v11 : v10;
    pa[2] = hi ? w01 : w00;
    pa[3] = hi ? w11 : w10;
}

// ---------------- GEMM: C[M,N] = W[M,K] * X[K,N] + bias[M] ----------------
__global__ __launch_bounds__(256) void gemm_bias_kernel(
    const float* __restrict__ W, const float* __restrict__ X,
    const float* __restrict__ bias, float* __restrict__ C,
    int M, int N, int K)
{
    __shared__ float Ws[16][65];
    __shared__ float Xs[16][64];
    int m0 = blockIdx.y * 64, n0 = blockIdx.x * 64;
    int tx = threadIdx.x & 15, ty = threadIdx.x >> 4;
    float acc[4][4];
    #pragma unroll
    for (int i = 0; i < 4; i++)
        #pragma unroll
        for (int j = 0; j < 4; j++) acc[i][j] = 0.f;

    for (int k0 = 0; k0 < K; k0 += 16) {
        #pragma unroll
        for (int r = 0; r < 4; r++) {
            int i = threadIdx.x + r * 256;
            int k = i & 15, mm = i >> 4;
            Ws[k][mm] = W[(m0 + mm) * K + k0 + k];
        }
        #pragma unroll
        for (int r = 0; r < 4; r++) {
            int i = threadIdx.x + r * 256;
            int n = i & 63, k = i >> 6;
            Xs[k][n] = X[(size_t)(k0 + k) * N + n0 + n];
        }
        __syncthreads();
        #pragma unroll
        for (int k = 0; k < 16; k++) {
            float wr[4], xr[4];
            #pragma unroll
            for (int i = 0; i < 4; i++) wr[i] = Ws[k][ty * 4 + i];
            #pragma unroll
            for (int j = 0; j < 4; j++) xr[j] = Xs[k][tx * 4 + j];
            #pragma unroll
            for (int i = 0; i < 4; i++)
                #pragma unroll
                for (int j = 0; j < 4; j++) acc[i][j] += wr[i] * xr[j];
        }
        __syncthreads();
    }
    #pragma unroll
    for (int i = 0; i < 4; i++) {
        float b = bias[m0 + ty * 4 + i];
        #pragma unroll
        for (int j = 0; j < 4; j++)
            C[(size_t)(m0 + ty * 4 + i) * N + n0 + tx * 4 + j] = acc[i][j] + b;
    }
}

// ---------------- 3x3 depthwise conv ----------------
__global__ __launch_bounds__(256) void dwconv_kernel(
    const float* __restrict__ in, const float* __restrict__ w,
    const float* __restrict__ b, float* __restrict__ out)
{
    int c = blockIdx.y;
    int pix = blockIdx.x * 256 + threadIdx.x;
    int y = pix >> 6, x = pix & 63;
    const float* wp = w + c * 9;
    const float* ip = in + (size_t)c * HW;
    float acc = b[c];
    #pragma unroll
    for (int ky = 0; ky < 3; ky++) {
        int yy = y + ky - 1;
        if (yy < 0 || yy > 63) continue;
        #pragma unroll
        for (int kx = 0; kx < 3; kx++) {
            int xx = x + kx - 1;
            if (xx < 0 || xx > 63) continue;
            acc += wp[ky * 3 + kx] * ip[yy * 64 + xx];
        }
    }
    out[(size_t)c * HW + pix] = acc;
}

// ---------------- per-(head,n) inverse L2 norms ----------------
__global__ __launch_bounds__(256) void norm_kernel(
    const float* __restrict__ qkv, float* __restrict__ invq, float* __restrict__ invk)
{
    int idx = blockIdx.x * 256 + threadIdx.x;
    int h = idx / HW, n = idx % HW;
    const float* qb = qkv + (size_t)(h * D) * HW + n;
    const float* kb = qkv + (size_t)(DIM + h * D) * HW + n;
    float sq = 0.f, sk = 0.f;
    #pragma unroll
    for (int d = 0; d < D; d++) {
        float a = qb[(size_t)d * HW]; sq += a * a;
        float c = kb[(size_t)d * HW]; sk += c * c;
    }
    invq[idx] = 1.0f / fmaxf(sqrtf(sq), 1e-12f);
    invk[idx] = 1.0f / fmaxf(sqrtf(sk), 1e-12f);
}

// ---------------- attention via mma.sync tf32, split over keys ----------------
// CTA: 128 queries x 1 head x SKEYS keys. 4 warps, 32 queries/warp (2 row-blocks).
// No softmax max/rescale: |score| <= temp (q,k L2-normalized); scale folded into Q.
__global__ __launch_bounds__(128, 3) void flash_mma_kernel(
    const float* __restrict__ qkv, const float* __restrict__ invq,
    const float* __restrict__ invk, const float* __restrict__ temp,
    float* __restrict__ po, float* __restrict__ pl)
{
    extern __shared__ float sm[];
    float* Qf = sm + QF_OFF;
    float* Kf = sm + KF_OFF;
    float* Vf = sm + VF_OFF;

    int tid = threadIdx.x, w = tid >> 5, lane = tid & 31;
    int g = lane >> 2, tig = lane & 3;
    int h = blockIdx.y, sp = blockIdx.z;
    int n0 = blockIdx.x * 128;

    const float* qg  = qkv + (size_t)(h * D) * HW;
    const float* kg  = qkv + (size_t)(DIM + h * D) * HW;
    const float* vg  = qkv + (size_t)(2 * DIM + h * D) * HW;
    const float* ikp = invk + h * HW;
    float cst = temp[h] * 1.44269504088896f;   // temp * log2(e)

    // Q -> fragment-order smem (invq * cst folded, tf32-rounded)
    for (int i = tid; i < 128 * D; i += 128) {
        int q = i & 127, d = i >> 7;
        int ww = q >> 5, rb = (q >> 4) & 1, r15 = q & 15;
        int gg = r15 & 7, rhi = r15 >> 3;
        int s = d >> 3, t4 = d & 7, tg = t4 & 3, hi = t4 >> 2;
        float val = qg[(size_t)d * HW + n0 + q] * invq[h * HW + n0 + q] * cst;
        Qf[((((ww * 2 + rb) * 6 + s) * 32 + gg * 4 + tg) * 4) + ((hi << 1) | rhi)]
            = __uint_as_float(f2tf(val));
    }

    float oacc[2][6][4];
    float lsum[2][2] = {{0.f, 0.f}, {0.f, 0.f}};
    #pragma unroll
    for (int rb = 0; rb < 2; rb++)
        #pragma unroll
        for (int j = 0; j < 6; j++)
            #pragma unroll
            for (int e = 0; e < 4; e++) oacc[rb][j][e] = 0.f;

    int kbeg = sp * SKEYS;
    for (int t = 0; t < NTT; t++) {
        int kb = kbeg + t * BKT;
        __syncthreads();   // prior tile's frags fully consumed
        // K, V -> fragment-order smem
        for (int i = tid; i < BKT * D; i += 128) {
            int key = i & 63, d = i >> 6;
            float kv = kg[(size_t)d * HW + kb + key] * ikp[kb + key];
            int j = key >> 3, gg = key & 7;
            int s = d >> 3, t4 = d & 7, tg = t4 & 3, r = t4 >> 2;
            Kf[(((s * 8 + j) * 32) + gg * 4 + tg) * 2 + r] = __uint_as_float(f2tf(kv));
            float vv = vg[(size_t)d * HW + kb + key];
            int s2 = key >> 3, tt = key & 7, tg2 = tt & 3, r2 = tt >> 2;
            int j2 = d >> 3, g2 = d & 7;
            Vf[(((s2 * 6 + j2) * 32) + g2 * 4 + tg2) * 2 + r2] = __uint_as_float(f2tf(vv));
        }
        __syncthreads();

        // S = Q * K^T   (sacc[rb][j] covers rows 16, keys 8j..8j+7)
        float sacc[2][8][4];
        #pragma unroll
        for (int rb = 0; rb < 2; rb++)
            #pragma unroll
            for (int j = 0; j < 8; j++)
                #pragma unroll
                for (int e = 0; e < 4; e++) sacc[rb][j][e] = 0.f;

        #pragma unroll
        for (int s = 0; s < 6; s++) {
            float4 q0 = *(const float4*)&Qf[(((w * 2 + 0) * 6 + s) * 32 + lane) * 4];
            float4 q1 = *(const float4*)&Qf[(((w * 2 + 1) * 6 + s) * 32 + lane) * 4];
            #pragma unroll
            for (int j = 0; j < 8; j++) {
                float2 kb2 = *(const float2*)&Kf[((s * 8 + j) * 32 + lane) * 2];
                mma8(sacc[0][j], (const float*)&q0, kb2);
                mma8(sacc[1][j], (const float*)&q1, kb2);
            }
        }

        // P = exp2(S), row sums, tf32 round in place
        #pragma unroll
        for (int rb = 0; rb < 2; rb++)
            #pragma unroll
            for (int j = 0; j < 8; j++)
                #pragma unroll
                for (int e = 0; e < 4; e++) {
                    float p = ex2f(sacc[rb][j][e]);
                    lsum[rb][e >> 1] += p;
                    sacc[rb][j][e] = __uint_as_float(f2tf(p));
                }

        // O += P * V
        #pragma unroll
        for (int s2 = 0; s2 < 8; s2++) {
            float pa0[4], pa1[4];
            make_pa(sacc[0][s2], pa0, lane);
            make_pa(sacc[1][s2], pa1, lane);
            #pragma unroll
            for (int j2 = 0; j2 < 6; j2++) {
                float2 vb = *(const float2*)&Vf[((s2 * 6 + j2) * 32 + lane) * 2];
                mma8(oacc[0][j2], pa0, vb);
                mma8(oacc[1][j2], pa1, vb);
            }
        }
    }

    // reduce row sums across the quad (cols are spread over tig)
    #pragma unroll
    for (int rb = 0; rb < 2; rb++)
        #pragma unroll
        for (int i = 0; i < 2; i++) {
            float v = lsum[rb][i];
            v += __shfl_xor_sync(0xffffffffu, v, 1);
            v += __shfl_xor_sync(0xffffffffu, v, 2);
            lsum[rb][i] = v;
        }

    int sh = sp * HEADS + h;
    if (tig == 0) {
        #pragma unroll
        for (int rb = 0; rb < 2; rb++) {
            int row = n0 + w * 32 + rb * 16 + g;
            pl[(size_t)sh * HW + row]     = lsum[rb][0];
            pl[(size_t)sh * HW + row + 8] = lsum[rb][1];
        }
    }
    #pragma unroll
    for (int rb = 0; rb < 2; rb++)
        #pragma unroll
        for (int j2 = 0; j2 < 6; j2++)
            #pragma unroll
            for (int e = 0; e < 4; e++) {
                int row = n0 + w * 32 + rb * 16 + g + ((e >> 1) << 3);
                int d = 8 * j2 + 2 * tig + (e & 1);
                po[(size_t)(sh * D + d) * HW + row] = oacc[rb][j2][e];
            }
}

// ---------------- combine split partials (no max needed) ----------------
__global__ __launch_bounds__(256) void combine_kernel(
    const float* __restrict__ po, const float* __restrict__ pl,
    float* __restrict__ att)
{
    int idx = blockIdx.x * 256 + threadIdx.x;   // 0 .. HEADS*HW-1
    int h = idx / HW, n = idx % HW;
    float L = 0.f;
    #pragma unroll
    for (int s = 0; s < SPLITS; s++)
        L += pl[(size_t)(s * HEADS + h) * HW + n];
    float Linv = 1.0f / L;
    #pragma unroll
    for (int d = 0; d < D; d++) {
        float acc = 0.f;
        #pragma unroll
        for (int s = 0; s < SPLITS; s++)
            acc += po[(size_t)((s * HEADS + h) * D + d) * HW + n];
        att[(size_t)(h * D + d) * HW + n] = acc * Linv;
    }
}

// ---------------- launch ----------------
extern "C" void kernel_launch(void* const* d_in, const int* in_sizes, int n_in,
                              void* d_out, int out_size)
{
    const float* x      = (const float*)d_in[0];
    const float* w_qkv  = (const float*)d_in[1];
    const float* b_qkv  = (const float*)d_in[2];
    const float* w_dw   = (const float*)d_in[3];
    const float* b_dw   = (const float*)d_in[4];
    const float* w_proj = (const float*)d_in[5];
    const float* b_proj = (const float*)d_in[6];
    const float* temp   = (const float*)d_in[7];
    float* out = (float*)d_out;

    float *qkv1, *qkv2, *invq, *invk, *att, *po, *pl;
    cudaGetSymbolAddress((void**)&qkv1, g_qkv1);
    cudaGetSymbolAddress((void**)&qkv2, g_qkv2);
    cudaGetSymbolAddress((void**)&invq, g_invq);
    cudaGetSymbolAddress((void**)&invk, g_invk);
    cudaGetSymbolAddress((void**)&att,  g_att);
    cudaGetSymbolAddress((void**)&po,   g_po);
    cudaGetSymbolAddress((void**)&pl,   g_pl);

    cudaFuncSetAttribute(flash_mma_kernel,
                         cudaFuncAttributeMaxDynamicSharedMemorySize,
                         SMEM_FLOATS * 4);

    // 1) qkv 1x1 conv
    {
        dim3 grid(HW / 64, (3 * DIM) / 64);
        gemm_bias_kernel<<<grid, 256>>>(w_qkv, x, b_qkv, qkv1, 3 * DIM, HW, DIM);
    }
    // 2) depthwise
    {
        dim3 grid(HW / 256, 3 * DIM);
        dwconv_kernel<<<grid, 256>>>(qkv1, w_dw, b_dw, qkv2);
    }
    // 3) inverse norms
    norm_kernel<<<(HEADS * HW) / 256, 256>>>(qkv2, invq, invk);
    // 4) attention (tensor-core mma.sync, split over keys)
    {
        dim3 grid(HW / 128, HEADS, SPLITS);
        flash_mma_kernel<<<grid, 128, SMEM_FLOATS * 4>>>(qkv2, invq, invk, temp, po, pl);
    }
    // 5) combine
    combine_kernel<<<(HEADS * HW) / 256, 256>>>(po, pl, att);
    // 6) output projection
    {
        dim3 grid(HW / 64, DIM / 64);
        gemm_bias_kernel<<<grid, 256>>>(w_proj, att, b_proj, out, DIM, HW, DIM);
    }
}

// round 7
// speedup vs baseline: 7.1196x; 1.4956x over previous
#include <cuda_runtime.h>
#include <cuda_bf16.h>
#include <cstdint>

#define DIM    192
#define HEADS  4
#define D      48
#define HW     4096
#define BKT    64              // keys per tile
#define SPLITS 8
#define SKEYS  (HW / SPLITS)   // 512 keys per split
#define NTT    (SKEYS / BKT)   // 8 tiles per split

// fragment array sizes (in base elements)
#define QF_LANES (HEADS * 256 * 6 * 32)          // float4 entries = 196608
#define KF_LANES (HEADS * 64 * 6 * 8 * 32)       // float2 entries = 393216
#define VF_LANES (HEADS * 64 * 4 * 6 * 32)       // uint2  entries = 196608

// ---------------- scratch ----------------
__device__ float g_qkv1[3 * DIM * HW];
__device__ float g_qkv2[3 * DIM * HW];
__device__ float g_invq[HEADS * HW];
__device__ float g_invk[HEADS * HW];
__device__ float g_att [DIM * HW];
__device__ float g_po  [SPLITS * DIM * HW];
__device__ float g_pl  [SPLITS * HEADS * HW];
__device__ float4 g_Qf [QF_LANES];
__device__ float2 g_Kf [KF_LANES];
__device__ uint2  g_Vf [VF_LANES];

// ---------------- helpers ----------------
__device__ __forceinline__ uint32_t f2tf(float x) {
    uint32_t y; asm("cvt.rna.tf32.f32 %0, %1;" : "=r"(y) : "f"(x)); return y;
}
__device__ __forceinline__ float ex2f(float x) {
    float y; asm("ex2.approx.f32 %0, %1;" : "=f"(y) : "f"(x)); return y;
}
// pack two f32 -> f16x2 (lo = second operand)
__device__ __forceinline__ uint32_t packh(float hi, float lo) {
    uint32_t r; asm("cvt.rn.f16x2.f32 %0, %1, %2;" : "=r"(r) : "f"(hi), "f"(lo));
    return r;
}
// D += A(16x8 tf32) * B(8x8 tf32)
__device__ __forceinline__ void mma8(float* d, const float* a, float2 b) {
    asm volatile("mma.sync.aligned.m16n8k8.row.col.f32.tf32.tf32.f32 "
        "{%0,%1,%2,%3}, {%4,%5,%6,%7}, {%8,%9}, {%0,%1,%2,%3};"
        : "+f"(d[0]), "+f"(d[1]), "+f"(d[2]), "+f"(d[3])
        : "r"(__float_as_uint(a[0])), "r"(__float_as_uint(a[1])),
          "r"(__float_as_uint(a[2])), "r"(__float_as_uint(a[3])),
          "r"(__float_as_uint(b.x)),  "r"(__float_as_uint(b.y)));
}
// D += A(16x16 f16) * B(16x8 f16)
__device__ __forceinline__ void mma16(float* d, const uint32_t* a, uint2 b) {
    asm volatile("mma.sync.aligned.m16n8k16.row.col.f32.f16.f16.f32 "
        "{%0,%1,%2,%3}, {%4,%5,%6,%7}, {%8,%9}, {%0,%1,%2,%3};"
        : "+f"(d[0]), "+f"(d[1]), "+f"(d[2]), "+f"(d[3])
        : "r"(a[0]), "r"(a[1]), "r"(a[2]), "r"(a[3]),
          "r"(b.x), "r"(b.y));
}

// ---------------- GEMM: C[M,N] = W[M,K] * X[K,N] + bias[M] ----------------
__global__ __launch_bounds__(256) void gemm_bias_kernel(
    const float* __restrict__ W, const float* __restrict__ X,
    const float* __restrict__ bias, float* __restrict__ C,
    int M, int N, int K)
{
    __shared__ float Ws[16][65];
    __shared__ float Xs[16][64];
    int m0 = blockIdx.y * 64, n0 = blockIdx.x * 64;
    int tx = threadIdx.x & 15, ty = threadIdx.x >> 4;
    float acc[4][4];
    #pragma unroll
    for (int i = 0; i < 4; i++)
        #pragma unroll
        for (int j = 0; j < 4; j++) acc[i][j] = 0.f;

    for (int k0 = 0; k0 < K; k0 += 16) {
        #pragma unroll
        for (int r = 0; r < 4; r++) {
            int i = threadIdx.x + r * 256;
            int k = i & 15, mm = i >> 4;
            Ws[k][mm] = W[(m0 + mm) * K + k0 + k];
        }
        #pragma unroll
        for (int r = 0; r < 4; r++) {
            int i = threadIdx.x + r * 256;
            int n = i & 63, k = i >> 6;
            Xs[k][n] = X[(size_t)(k0 + k) * N + n0 + n];
        }
        __syncthreads();
        #pragma unroll
        for (int k = 0; k < 16; k++) {
            float wr[4], xr[4];
            #pragma unroll
            for (int i = 0; i < 4; i++) wr[i] = Ws[k][ty * 4 + i];
            #pragma unroll
            for (int j = 0; j < 4; j++) xr[j] = Xs[k][tx * 4 + j];
            #pragma unroll
            for (int i = 0; i < 4; i++)
                #pragma unroll
                for (int j = 0; j < 4; j++) acc[i][j] += wr[i] * xr[j];
        }
        __syncthreads();
    }
    #pragma unroll
    for (int i = 0; i < 4; i++) {
        float b = bias[m0 + ty * 4 + i];
        #pragma unroll
        for (int j = 0; j < 4; j++)
            C[(size_t)(m0 + ty * 4 + i) * N + n0 + tx * 4 + j] = acc[i][j] + b;
    }
}

// ---------------- 3x3 depthwise conv ----------------
__global__ __launch_bounds__(256) void dwconv_kernel(
    const float* __restrict__ in, const float* __restrict__ w,
    const float* __restrict__ b, float* __restrict__ out)
{
    int c = blockIdx.y;
    int pix = blockIdx.x * 256 + threadIdx.x;
    int y = pix >> 6, x = pix & 63;
    const float* wp = w + c * 9;
    const float* ip = in + (size_t)c * HW;
    float acc = b[c];
    #pragma unroll
    for (int ky = 0; ky < 3; ky++) {
        int yy = y + ky - 1;
        if (yy < 0 || yy > 63) continue;
        #pragma unroll
        for (int kx = 0; kx < 3; kx++) {
            int xx = x + kx - 1;
            if (xx < 0 || xx > 63) continue;
            acc += wp[ky * 3 + kx] * ip[yy * 64 + xx];
        }
    }
    out[(size_t)c * HW + pix] = acc;
}

// ---------------- per-(head,n) inverse L2 norms ----------------
__global__ __launch_bounds__(256) void norm_kernel(
    const float* __restrict__ qkv, float* __restrict__ invq, float* __restrict__ invk)
{
    int idx = blockIdx.x * 256 + threadIdx.x;
    int h = idx / HW, n = idx % HW;
    const float* qb = qkv + (size_t)(h * D) * HW + n;
    const float* kb = qkv + (size_t)(DIM + h * D) * HW + n;
    float sq = 0.f, sk = 0.f;
    #pragma unroll
    for (int d = 0; d < D; d++) {
        float a = qb[(size_t)d * HW]; sq += a * a;
        float c = kb[(size_t)d * HW]; sk += c * c;
    }
    invq[idx] = 1.0f / fmaxf(sqrtf(sq), 1e-12f);
    invk[idx] = 1.0f / fmaxf(sqrtf(sk), 1e-12f);
}

// ---------------- build Q/K/V fragment arrays in gmem ----------------
// Qf[h][rb16(256)][s(6)][lane] float4 : tf32 A-frags of Q*(invq*temp*log2e)
// Kf[h][t(64)][s(6)][j(8)][lane] float2 : tf32 B-frags of normalized K
// Vf[h][t(64)][u(4)][j2(6)][lane] uint2 : f16x2 B-frags (m16n8k16) of V
__global__ __launch_bounds__(256) void prep_kernel(
    const float* __restrict__ qkv, const float* __restrict__ invq,
    const float* __restrict__ invk, const float* __restrict__ temp,
    float4* __restrict__ Qf, float2* __restrict__ Kf, uint2* __restrict__ Vf)
{
    int idx = blockIdx.x * 256 + threadIdx.x;
    if (idx < QF_LANES) {
        int lane = idx & 31; int r = idx >> 5;
        int s = r % 6; r /= 6;
        int rb = r & 255; int h = r >> 8;
        int g = lane >> 2, tig = lane & 3;
        float cst = temp[h] * 1.44269504088896f;
        const float* qg = qkv + (size_t)(h * D) * HW;
        int row0 = rb * 16 + g;
        float iq0 = invq[h * HW + row0] * cst;
        float iq1 = invq[h * HW + row0 + 8] * cst;
        int d0 = 8 * s + tig;
        float4 v;
        v.x = __uint_as_float(f2tf(qg[(size_t)d0 * HW + row0] * iq0));
        v.y = __uint_as_float(f2tf(qg[(size_t)d0 * HW + row0 + 8] * iq1));
        v.z = __uint_as_float(f2tf(qg[(size_t)(d0 + 4) * HW + row0] * iq0));
        v.w = __uint_as_float(f2tf(qg[(size_t)(d0 + 4) * HW + row0 + 8] * iq1));
        Qf[idx] = v;
    } else if (idx < QF_LANES + KF_LANES) {
        int i = idx - QF_LANES;
        int lane = i & 31; int r = i >> 5;
        int j = r & 7; r >>= 3;
        int s = r % 6; r /= 6;
        int t = r & 63; int h = r >> 6;
        int g = lane >> 2, tig = lane & 3;
        int key = t * 64 + j * 8 + g;
        float ik = invk[h * HW + key];
        const float* kg = qkv + (size_t)(DIM + h * D) * HW;
        float2 v;
        v.x = __uint_as_float(f2tf(kg[(size_t)(8 * s + tig) * HW + key] * ik));
        v.y = __uint_as_float(f2tf(kg[(size_t)(8 * s + tig + 4) * HW + key] * ik));
        Kf[i] = v;
    } else if (idx < QF_LANES + KF_LANES + VF_LANES) {
        int i = idx - QF_LANES - KF_LANES;
        int lane = i & 31; int r = i >> 5;
        int j2 = r % 6; r /= 6;
        int u = r & 3; r >>= 2;
        int t = r & 63; int h = r >> 6;
        int g = lane >> 2, tig = lane & 3;
        int d = 8 * j2 + g;
        const float* vp = qkv + (size_t)(2 * DIM + h * D) * HW + (size_t)d * HW;
        int k0 = t * 64 + u * 16 + 2 * tig;
        uint2 o;
        o.x = packh(vp[k0 + 1], vp[k0]);       // lo = key k0, hi = k0+1
        o.y = packh(vp[k0 + 9], vp[k0 + 8]);
        Vf[i] = o;
    }
}

// ---------------- attention: tf32 QK + f16 PV, frags straight from gmem ----
// CTA: 128 queries x 1 head x SKEYS keys; 4 warps x 32 queries. No smem.
// No softmax max/rescale: |score| <= temp (q,k L2-normalized), scale in Qf.
__global__ __launch_bounds__(128, 3) void flash_mma_kernel(
    const float4* __restrict__ Qf, const float2* __restrict__ Kf,
    const uint2* __restrict__ Vf,
    float* __restrict__ po, float* __restrict__ pl)
{
    int tid = threadIdx.x, w = tid >> 5, lane = tid & 31;
    int g = lane >> 2, tig = lane & 3;
    int h = blockIdx.y, sp = blockIdx.z;
    int n0 = blockIdx.x * 128;
    int rb16 = (n0 >> 4) + w * 2;    // first of this warp's two 16-row blocks

    const float4* qf = Qf + ((size_t)(h * 256 + rb16) * 6) * 32 + lane;

    float oacc[2][6][4];
    float lsum[2][2] = {{0.f, 0.f}, {0.f, 0.f}};
    #pragma unroll
    for (int rb = 0; rb < 2; rb++)
        #pragma unroll
        for (int j = 0; j < 6; j++)
            #pragma unroll
            for (int e = 0; e < 4; e++) oacc[rb][j][e] = 0.f;

    int t0 = sp * NTT;
    for (int tt = 0; tt < NTT; tt++) {
        int t = t0 + tt;
        const float2* kf = Kf + ((size_t)(h * 64 + t) * 48) * 32 + lane;
        const uint2*  vf = Vf + ((size_t)(h * 64 + t) * 24) * 32 + lane;

        // S = Q * K^T
        float sacc[2][8][4];
        #pragma unroll
        for (int rb = 0; rb < 2; rb++)
            #pragma unroll
            for (int j = 0; j < 8; j++)
                #pragma unroll
                for (int e = 0; e < 4; e++) sacc[rb][j][e] = 0.f;

        #pragma unroll
        for (int s = 0; s < 6; s++) {
            float4 q0 = qf[s * 32];
            float4 q1 = qf[(6 + s) * 32];
            #pragma unroll
            for (int j = 0; j < 8; j++) {
                float2 kb = kf[(s * 8 + j) * 32];
                mma8(sacc[0][j], (const float*)&q0, kb);
                mma8(sacc[1][j], (const float*)&q1, kb);
            }
        }

        // P = exp2(S), row sums (f32 kept in sacc)
        #pragma unroll
        for (int rb = 0; rb < 2; rb++)
            #pragma unroll
            for (int j = 0; j < 8; j++)
                #pragma unroll
                for (int e = 0; e < 4; e++) {
                    float p = ex2f(sacc[rb][j][e]);
                    lsum[rb][e >> 1] += p;
                    sacc[rb][j][e] = p;
                }

        // pack P into f16 A-frags: C-frag pairs map directly, no shuffles
        uint32_t pf[2][4][4];
        #pragma unroll
        for (int rb = 0; rb < 2; rb++)
            #pragma unroll
            for (int u = 0; u < 4; u++) {
                pf[rb][u][0] = packh(sacc[rb][2 * u][1],     sacc[rb][2 * u][0]);
                pf[rb][u][1] = packh(sacc[rb][2 * u][3],     sacc[rb][2 * u][2]);
                pf[rb][u][2] = packh(sacc[rb][2 * u + 1][1], sacc[rb][2 * u + 1][0]);
                pf[rb][u][3] = packh(sacc[rb][2 * u + 1][3], sacc[rb][2 * u + 1][2]);
            }

        // O += P * V  (f16 m16n8k16)
        #pragma unroll
        for (int u = 0; u < 4; u++)
            #pragma unroll
            for (int j2 = 0; j2 < 6; j2++) {
                uint2 vb = vf[(u * 6 + j2) * 32];
                mma16(oacc[0][j2], pf[0][u], vb);
                mma16(oacc[1][j2], pf[1][u], vb);
            }
    }

    // reduce row sums across the quad
    #pragma unroll
    for (int rb = 0; rb < 2; rb++)
        #pragma unroll
        for (int i = 0; i < 2; i++) {
            float v = lsum[rb][i];
            v += __shfl_xor_sync(0xffffffffu, v, 1);
            v += __shfl_xor_sync(0xffffffffu, v, 2);
            lsum[rb][i] = v;
        }

    int sh = sp * HEADS + h;
    if (tig == 0) {
        #pragma unroll
        for (int rb = 0; rb < 2; rb++) {
            int row = n0 + w * 32 + rb * 16 + g;
            pl[(size_t)sh * HW + row]     = lsum[rb][0];
            pl[(size_t)sh * HW + row + 8] = lsum[rb][1];
        }
    }
    #pragma unroll
    for (int rb = 0; rb < 2; rb++)
        #pragma unroll
        for (int j2 = 0; j2 < 6; j2++)
            #pragma unroll
            for (int e = 0; e < 4; e++) {
                int row = n0 + w * 32 + rb * 16 + g + ((e >> 1) << 3);
                int d = 8 * j2 + 2 * tig + (e & 1);
                po[(size_t)(sh * D + d) * HW + row] = oacc[rb][j2][e];
            }
}

// ---------------- combine split partials ----------------
__global__ __launch_bounds__(256) void combine_kernel(
    const float* __restrict__ po, const float* __restrict__ pl,
    float* __restrict__ att)
{
    int idx = blockIdx.x * 256 + threadIdx.x;
    int h = idx / HW, n = idx % HW;
    float L = 0.f;
    #pragma unroll
    for (int s = 0; s < SPLITS; s++)
        L += pl[(size_t)(s * HEADS + h) * HW + n];
    float Linv = 1.0f / L;
    #pragma unroll
    for (int d = 0; d < D; d++) {
        float acc = 0.f;
        #pragma unroll
        for (int s = 0; s < SPLITS; s++)
            acc += po[(size_t)((s * HEADS + h) * D + d) * HW + n];
        att[(size_t)(h * D + d) * HW + n] = acc * Linv;
    }
}

// ---------------- launch ----------------
extern "C" void kernel_launch(void* const* d_in, const int* in_sizes, int n_in,
                              void* d_out, int out_size)
{
    const float* x      = (const float*)d_in[0];
    const float* w_qkv  = (const float*)d_in[1];
    const float* b_qkv  = (const float*)d_in[2];
    const float* w_dw   = (const float*)d_in[3];
    const float* b_dw   = (const float*)d_in[4];
    const float* w_proj = (const float*)d_in[5];
    const float* b_proj = (const float*)d_in[6];
    const float* temp   = (const float*)d_in[7];
    float* out = (float*)d_out;

    float *qkv1, *qkv2, *invq, *invk, *att, *po, *pl;
    float4* Qf; float2* Kf; uint2* Vf;
    cudaGetSymbolAddress((void**)&qkv1, g_qkv1);
    cudaGetSymbolAddress((void**)&qkv2, g_qkv2);
    cudaGetSymbolAddress((void**)&invq, g_invq);
    cudaGetSymbolAddress((void**)&invk, g_invk);
    cudaGetSymbolAddress((void**)&att,  g_att);
    cudaGetSymbolAddress((void**)&po,   g_po);
    cudaGetSymbolAddress((void**)&pl,   g_pl);
    cudaGetSymbolAddress((void**)&Qf,   g_Qf);
    cudaGetSymbolAddress((void**)&Kf,   g_Kf);
    cudaGetSymbolAddress((void**)&Vf,   g_Vf);

    // 1) qkv 1x1 conv
    {
        dim3 grid(HW / 64, (3 * DIM) / 64);
        gemm_bias_kernel<<<grid, 256>>>(w_qkv, x, b_qkv, qkv1, 3 * DIM, HW, DIM);
    }
    // 2) depthwise
    {
        dim3 grid(HW / 256, 3 * DIM);
        dwconv_kernel<<<grid, 256>>>(qkv1, w_dw, b_dw, qkv2);
    }
    // 3) inverse norms
    norm_kernel<<<(HEADS * HW) / 256, 256>>>(qkv2, invq, invk);
    // 4) build fragment arrays
    {
        int total = QF_LANES + KF_LANES + VF_LANES;
        prep_kernel<<<(total + 255) / 256, 256>>>(qkv2, invq, invk, temp, Qf, Kf, Vf);
    }
    // 5) attention
    {
        dim3 grid(HW / 128, HEADS, SPLITS);
        flash_mma_kernel<<<grid, 128>>>(Qf, Kf, Vf, po, pl);
    }
    // 6) combine
    combine_kernel<<<(HEADS * HW) / 256, 256>>>(po, pl, att);
    // 7) output projection
    {
        dim3 grid(HW / 64, DIM / 64);
        gemm_bias_kernel<<<grid, 256>>>(w_proj, att, b_proj, out, DIM, HW, DIM);
    }
}